// round 6
// baseline (speedup 1.0000x reference)
#include <cuda_runtime.h>
#include <cstdint>

// ---------------------------------------------------------------------------
// TimeMix collapses to: out = (sigmoid(xr @ Wr^T) * (xv @ Wv^T or wkv@t0)) @ Wo^T
// where xv = x*tmv + (1-tmv)*xx, xr likewise. For t>0 the padded state is all
// zeros so wkv == v exactly; only the 4 rows at t==0 need the full wkv formula
// (handled by a tiny per-row correction that computes k = xk @ Wk^T for t=0).
// ---------------------------------------------------------------------------

namespace {
constexpr int  BDIM = 4;
constexpr int  TDIM = 2048;
constexpr int  CDIM = 2048;
constexpr long MDIM = (long)BDIM * TDIM;   // 8192 rows (B*T)
constexpr int  KDIM = CDIM;                // 2048
constexpr int  NDIM = CDIM;                // 2048

constexpr int BM = 128, BN = 128, BK = 16;
constexpr int LSTR = 20;                    // padded smem row stride (floats)
constexpr int SMEM_FLOATS = 2 * 2 * BM * LSTR;   // 10240 floats = 40 KB
}

// Scratch (static device allocations — allowed; no cudaMalloc anywhere)
__device__ float g_xv[MDIM * KDIM];
__device__ float g_xr[MDIM * KDIM];
__device__ float g_v [MDIM * NDIM];
__device__ float g_rv[MDIM * NDIM];
__device__ float g_wv[(long)NDIM * KDIM];
__device__ float g_wr[(long)NDIM * KDIM];
__device__ float g_wo[(long)NDIM * KDIM];

__device__ __forceinline__ float rna_tf32(float f) {
    uint32_t u;
    asm("cvt.rna.tf32.f32 %0, %1;" : "=r"(u) : "f"(f));
    return __uint_as_float(u);
}

__device__ __forceinline__ void cp16(uint32_t s, const void* g) {
    asm volatile("cp.async.cg.shared.global [%0], [%1], 16;" :: "r"(s), "l"(g));
}

// ---- round the three live weight matrices to tf32 (removes truncation bias)
__global__ void prep_w_kernel(const float* __restrict__ wv,
                              const float* __restrict__ wr,
                              const float* __restrict__ wo) {
    long i = ((long)blockIdx.x * blockDim.x + threadIdx.x) * 4;
    float4 a = *(const float4*)(wv + i);
    float4 b = *(const float4*)(wr + i);
    float4 c = *(const float4*)(wo + i);
    a.x = rna_tf32(a.x); a.y = rna_tf32(a.y); a.z = rna_tf32(a.z); a.w = rna_tf32(a.w);
    b.x = rna_tf32(b.x); b.y = rna_tf32(b.y); b.z = rna_tf32(b.z); b.w = rna_tf32(b.w);
    c.x = rna_tf32(c.x); c.y = rna_tf32(c.y); c.z = rna_tf32(c.z); c.w = rna_tf32(c.w);
    *(float4*)(g_wv + i) = a;
    *(float4*)(g_wr + i) = b;
    *(float4*)(g_wo + i) = c;
}

// ---- token-mix + tf32 rounding for the two live GEMM A-operands
__global__ void prep_x_kernel(const float* __restrict__ x,
                              const float* __restrict__ tmv,
                              const float* __restrict__ tmr,
                              const float* __restrict__ xxp) {
    long i = ((long)blockIdx.x * blockDim.x + threadIdx.x) * 4;
    int  c = (int)(i & (CDIM - 1));
    float4 xv = *(const float4*)(x   + i);
    float4 mv = *(const float4*)(tmv + c);
    float4 mr = *(const float4*)(tmr + c);
    float4 xc = *(const float4*)(xxp + c);
    float4 ov, orr;
    ov.x  = rna_tf32(xv.x * mv.x + (1.f - mv.x) * xc.x);
    ov.y  = rna_tf32(xv.y * mv.y + (1.f - mv.y) * xc.y);
    ov.z  = rna_tf32(xv.z * mv.z + (1.f - mv.z) * xc.z);
    ov.w  = rna_tf32(xv.w * mv.w + (1.f - mv.w) * xc.w);
    orr.x = rna_tf32(xv.x * mr.x + (1.f - mr.x) * xc.x);
    orr.y = rna_tf32(xv.y * mr.y + (1.f - mr.y) * xc.y);
    orr.z = rna_tf32(xv.z * mr.z + (1.f - mr.z) * xc.z);
    orr.w = rna_tf32(xv.w * mr.w + (1.f - mr.w) * xc.w);
    *(float4*)(g_xv + i) = ov;
    *(float4*)(g_xr + i) = orr;
}

// ---- t==0 correction: compute full wkv for the 4 t=0 rows, overwrite g_v.
// One warp per output channel o; coalesced read of w_key row, warp reduce.
__global__ void t0_fix_kernel(const float* __restrict__ x,
                              const float* __restrict__ tf,
                              const float* __restrict__ tmk,
                              const float* __restrict__ xxp,
                              const float* __restrict__ aa,
                              const float* __restrict__ bb,
                              const float* __restrict__ pp,
                              const float* __restrict__ wk) {
    const int b    = blockIdx.y;
    const int o    = blockIdx.x * 8 + (threadIdx.x >> 5);
    const int lane = threadIdx.x & 31;
    const float* xrow = x  + (long)b * TDIM * CDIM;  // x[b][0][:]
    const float* wrow = wk + (long)o * CDIM;
    float s = 0.f;
    for (int c = lane; c < CDIM; c += 32) {
        float xk = xrow[c] * tmk[c] + (1.f - tmk[c]) * xxp[c];
        s += xk * wrow[c];
    }
    #pragma unroll
    for (int off = 16; off; off >>= 1) s += __shfl_xor_sync(0xffffffffu, s, off);
    if (lane == 0) {
        float ww = tf[o] + s;
        float p  = pp[o];
        float qq = fmaxf(p, ww);
        float e1 = expf(p  - qq);
        float e2 = expf(ww - qq);
        long idx = (long)b * TDIM * NDIM + o;   // row m = b*T + 0
        float v  = g_v[idx];
        g_v[idx] = (e1 * aa[o] + e2 * v) / (e1 * bb[o] + e2);
    }
}

// ---- tf32 mma.sync GEMM:  C[M,N] = A[M,K] @ W[N,K]^T
// MODE 0: g_v  = g_xv @ g_wv^T                      (plain f32 out)
// MODE 1: g_rv = rna_tf32( sigmoid(g_xr @ g_wr^T) * g_v )   (fused epilogue)
// MODE 2: out  = g_rv @ g_wo^T                      (plain f32 out)
template<int MODE>
__global__ void __launch_bounds__(256)
gemm_tf32(float* __restrict__ Cout) {
    const float* __restrict__ A = (MODE == 0) ? g_xv : (MODE == 1) ? g_xr : g_rv;
    const float* __restrict__ W = (MODE == 0) ? g_wv : (MODE == 1) ? g_wr : g_wo;
    float* __restrict__ Cp      = (MODE == 0) ? g_v  : (MODE == 1) ? g_rv : Cout;

    __shared__ float sm[SMEM_FLOATS];
    float* As = sm;
    float* Bs = sm + 2 * BM * LSTR;

    const int tid  = threadIdx.x;
    const int lane = tid & 31;
    const int warp = tid >> 5;
    const int wm = warp & 1;          // 2 warps over M (64 rows each)
    const int wn = warp >> 1;         // 4 warps over N (32 cols each)
    const int g  = lane >> 2;
    const int t  = lane & 3;
    const long bm = (long)blockIdx.y * BM;
    const long bn = (long)blockIdx.x * BN;

    float acc[4][4][4];
    #pragma unroll
    for (int i = 0; i < 4; i++)
        #pragma unroll
        for (int j = 0; j < 4; j++)
            #pragma unroll
            for (int k = 0; k < 4; k++) acc[i][j][k] = 0.f;

    const uint32_t sAb = (uint32_t)__cvta_generic_to_shared(As);
    const uint32_t sBb = (uint32_t)__cvta_generic_to_shared(Bs);

    const int lrow = tid >> 2;          // 0..63
    const int lkc  = (tid & 3) * 4;     // 0,4,8,12
    const float* gA = A + (bm + lrow) * KDIM + lkc;
    const float* gB = W + (bn + lrow) * KDIM + lkc;
    const uint32_t dA = sAb + (uint32_t)(lrow * LSTR + lkc) * 4u;
    const uint32_t dB = sBb + (uint32_t)(lrow * LSTR + lkc) * 4u;

    #define LOAD_STAGE(s, kt) do {                                        \
        int k0 = (kt) * BK;                                               \
        uint32_t so = (uint32_t)(s) * BM * LSTR * 4u;                     \
        cp16(dA + so,                  gA + k0);                          \
        cp16(dA + so + 64u*LSTR*4u,    gA + (long)64 * KDIM + k0);        \
        cp16(dB + so,                  gB + k0);                          \
        cp16(dB + so + 64u*LSTR*4u,    gB + (long)64 * KDIM + k0);        \
        asm volatile("cp.async.commit_group;");                           \
    } while (0)

    LOAD_STAGE(0, 0);

    const int NK = KDIM / BK;   // 128
    for (int kt = 0; kt < NK; ++kt) {
        asm volatile("cp.async.wait_group 0;");
        __syncthreads();
        if (kt + 1 < NK) LOAD_STAGE((kt + 1) & 1, kt + 1);
        const float* As_ = As + (kt & 1) * BM * LSTR;
        const float* Bs_ = Bs + (kt & 1) * BM * LSTR;
        #pragma unroll
        for (int ks = 0; ks < 2; ks++) {
            float a[4][4], b[4][2];
            #pragma unroll
            for (int im = 0; im < 4; im++) {
                const float* p = As_ + (wm * 64 + im * 16 + g) * LSTR + ks * 8 + t;
                a[im][0] = p[0];
                a[im][1] = p[8 * LSTR];
                a[im][2] = p[4];
                a[im][3] = p[8 * LSTR + 4];
            }
            #pragma unroll
            for (int in = 0; in < 4; in++) {
                const float* p = Bs_ + (wn * 32 + in * 8 + g) * LSTR + ks * 8 + t;
                b[in][0] = p[0];
                b[in][1] = p[4];
            }
            #pragma unroll
            for (int im = 0; im < 4; im++)
                #pragma unroll
                for (int in = 0; in < 4; in++)
                    asm volatile(
                        "mma.sync.aligned.m16n8k8.row.col.f32.tf32.tf32.f32 "
                        "{%0,%1,%2,%3}, {%4,%5,%6,%7}, {%8,%9}, {%0,%1,%2,%3};"
                        : "+f"(acc[im][in][0]), "+f"(acc[im][in][1]),
                          "+f"(acc[im][in][2]), "+f"(acc[im][in][3])
                        : "r"(__float_as_uint(a[im][0])), "r"(__float_as_uint(a[im][1])),
                          "r"(__float_as_uint(a[im][2])), "r"(__float_as_uint(a[im][3])),
                          "r"(__float_as_uint(b[in][0])), "r"(__float_as_uint(b[in][1])));
        }
    }
    #undef LOAD_STAGE

    // Epilogue: c0,c1 contiguous (cols t*2, t*2+1); c2,c3 at row+8.
    #pragma unroll
    for (int im = 0; im < 4; im++) {
        const long m0 = bm + wm * 64 + im * 16 + g;
        #pragma unroll
        for (int in = 0; in < 4; in++) {
            const long n0 = bn + wn * 32 + in * 8 + t * 2;
            const long i0 = m0 * NDIM + n0;
            const long i1 = i0 + 8L * NDIM;
            float c0 = acc[im][in][0], c1 = acc[im][in][1];
            float c2 = acc[im][in][2], c3 = acc[im][in][3];
            if (MODE == 1) {
                float2 v0 = *(const float2*)(g_v + i0);
                float2 v1 = *(const float2*)(g_v + i1);
                float r0 = 1.f / (1.f + __expf(-c0));
                float r1 = 1.f / (1.f + __expf(-c1));
                float r2 = 1.f / (1.f + __expf(-c2));
                float r3 = 1.f / (1.f + __expf(-c3));
                *(float2*)(Cp + i0) = make_float2(rna_tf32(r0 * v0.x), rna_tf32(r1 * v0.y));
                *(float2*)(Cp + i1) = make_float2(rna_tf32(r2 * v1.x), rna_tf32(r3 * v1.y));
            } else {
                *(float2*)(Cp + i0) = make_float2(c0, c1);
                *(float2*)(Cp + i1) = make_float2(c2, c3);
            }
        }
    }
}

extern "C" void kernel_launch(void* const* d_in, const int* in_sizes, int n_in,
                              void* d_out, int out_size) {
    (void)in_sizes; (void)n_in; (void)out_size;
    const float* x   = (const float*)d_in[0];
    const float* tf  = (const float*)d_in[1];
    const float* tmk = (const float*)d_in[2];
    const float* tmv = (const float*)d_in[3];
    const float* tmr = (const float*)d_in[4];
    const float* xxp = (const float*)d_in[5];
    const float* aa  = (const float*)d_in[6];
    const float* bb  = (const float*)d_in[7];
    const float* pp  = (const float*)d_in[8];
    const float* wk  = (const float*)d_in[9];
    const float* wv  = (const float*)d_in[10];
    const float* wr  = (const float*)d_in[11];
    const float* wo  = (const float*)d_in[12];
    float* out = (float*)d_out;

    prep_w_kernel<<<(unsigned)(((long)NDIM * KDIM) / 1024), 256>>>(wv, wr, wo);
    prep_x_kernel<<<(unsigned)((MDIM * (long)KDIM) / 1024), 256>>>(x, tmv, tmr, xxp);

    dim3 grid((unsigned)(NDIM / BN), (unsigned)(MDIM / BM));
    gemm_tf32<0><<<grid, 256>>>(nullptr);                       // g_v = xv @ Wv^T
    t0_fix_kernel<<<dim3(CDIM / 8, BDIM), 256>>>(x, tf, tmk, xxp, aa, bb, pp, wk);
    gemm_tf32<1><<<grid, 256>>>(nullptr);                       // g_rv = sig(xr@Wr^T) * g_v
    gemm_tf32<2><<<grid, 256>>>(out);                           // out = g_rv @ Wo^T
}

// round 8
// speedup vs baseline: 1.2086x; 1.2086x over previous
#include <cuda_runtime.h>
#include <cstdint>

// ---------------------------------------------------------------------------
// TimeMix collapses to: out = (sigmoid(xr @ Wr^T) * (xv @ Wv^T or wkv@t0)) @ Wo^T
// where xv = x*tmv + (1-tmv)*xx, xr likewise. For t>0 the padded state is all
// zeros so wkv == v exactly; only the 4 rows at t==0 need the full wkv formula.
// GEMM engine: legacy mma.sync tf32 (tcgen05 unavailable: harness targets
// compute_103, not 103a). This round: BK=32 + guaranteed 2 CTAs/SM to cut
// barrier/issue stalls.
// ---------------------------------------------------------------------------

namespace {
constexpr int  BDIM = 4;
constexpr int  TDIM = 2048;
constexpr int  CDIM = 2048;
constexpr long MDIM = (long)BDIM * TDIM;   // 8192 rows (B*T)
constexpr int  KDIM = CDIM;                // 2048
constexpr int  NDIM = CDIM;                // 2048

constexpr int BM = 128, BN = 128, BK = 32;
constexpr int LSTR = 36;                          // padded row stride (floats)
constexpr int MAT_FLOATS   = BM * LSTR;           // 4608 floats = 18432 B
constexpr int STAGE_FLOATS = 2 * MAT_FLOATS;      // A + B
constexpr int DYN_SMEM     = 2 * STAGE_FLOATS * 4;   // 73728 B
constexpr int NKT = KDIM / BK;                    // 64
}

// Scratch (static device arrays — no cudaMalloc anywhere)
__device__ float g_xv[MDIM * KDIM];
__device__ float g_xr[MDIM * KDIM];
__device__ float g_v [MDIM * NDIM];
__device__ float g_rv[MDIM * NDIM];
__device__ float g_wv[(long)NDIM * KDIM];
__device__ float g_wr[(long)NDIM * KDIM];
__device__ float g_wo[(long)NDIM * KDIM];

__device__ __forceinline__ float rna_tf32(float f) {
    uint32_t u;
    asm("cvt.rna.tf32.f32 %0, %1;" : "=r"(u) : "f"(f));
    return __uint_as_float(u);
}

__device__ __forceinline__ void cp16(uint32_t s, const void* g) {
    asm volatile("cp.async.cg.shared.global [%0], [%1], 16;" :: "r"(s), "l"(g));
}

// ---- round the three live weight matrices to tf32 (removes truncation bias)
__global__ void prep_w_kernel(const float* __restrict__ wv,
                              const float* __restrict__ wr,
                              const float* __restrict__ wo) {
    long i = ((long)blockIdx.x * blockDim.x + threadIdx.x) * 4;
    float4 a = *(const float4*)(wv + i);
    float4 b = *(const float4*)(wr + i);
    float4 c = *(const float4*)(wo + i);
    a.x = rna_tf32(a.x); a.y = rna_tf32(a.y); a.z = rna_tf32(a.z); a.w = rna_tf32(a.w);
    b.x = rna_tf32(b.x); b.y = rna_tf32(b.y); b.z = rna_tf32(b.z); b.w = rna_tf32(b.w);
    c.x = rna_tf32(c.x); c.y = rna_tf32(c.y); c.z = rna_tf32(c.z); c.w = rna_tf32(c.w);
    *(float4*)(g_wv + i) = a;
    *(float4*)(g_wr + i) = b;
    *(float4*)(g_wo + i) = c;
}

// ---- token-mix + tf32 rounding for the two live GEMM A-operands
__global__ void prep_x_kernel(const float* __restrict__ x,
                              const float* __restrict__ tmv,
                              const float* __restrict__ tmr,
                              const float* __restrict__ xxp) {
    long i = ((long)blockIdx.x * blockDim.x + threadIdx.x) * 4;
    int  c = (int)(i & (CDIM - 1));
    float4 xv = *(const float4*)(x   + i);
    float4 mv = *(const float4*)(tmv + c);
    float4 mr = *(const float4*)(tmr + c);
    float4 xc = *(const float4*)(xxp + c);
    float4 ov, orr;
    ov.x  = rna_tf32(xv.x * mv.x + (1.f - mv.x) * xc.x);
    ov.y  = rna_tf32(xv.y * mv.y + (1.f - mv.y) * xc.y);
    ov.z  = rna_tf32(xv.z * mv.z + (1.f - mv.z) * xc.z);
    ov.w  = rna_tf32(xv.w * mv.w + (1.f - mv.w) * xc.w);
    orr.x = rna_tf32(xv.x * mr.x + (1.f - mr.x) * xc.x);
    orr.y = rna_tf32(xv.y * mr.y + (1.f - mr.y) * xc.y);
    orr.z = rna_tf32(xv.z * mr.z + (1.f - mr.z) * xc.z);
    orr.w = rna_tf32(xv.w * mr.w + (1.f - mr.w) * xc.w);
    *(float4*)(g_xv + i) = ov;
    *(float4*)(g_xr + i) = orr;
}

// ---- t==0 correction: full wkv for the 4 t=0 rows, overwrite g_v.
__global__ void t0_fix_kernel(const float* __restrict__ x,
                              const float* __restrict__ tf,
                              const float* __restrict__ tmk,
                              const float* __restrict__ xxp,
                              const float* __restrict__ aa,
                              const float* __restrict__ bb,
                              const float* __restrict__ pp,
                              const float* __restrict__ wk) {
    const int b    = blockIdx.y;
    const int o    = blockIdx.x * 8 + (threadIdx.x >> 5);
    const int lane = threadIdx.x & 31;
    const float* xrow = x  + (long)b * TDIM * CDIM;
    const float* wrow = wk + (long)o * CDIM;
    float s = 0.f;
    for (int c = lane; c < CDIM; c += 32) {
        float xk = xrow[c] * tmk[c] + (1.f - tmk[c]) * xxp[c];
        s += xk * wrow[c];
    }
    #pragma unroll
    for (int off = 16; off; off >>= 1) s += __shfl_xor_sync(0xffffffffu, s, off);
    if (lane == 0) {
        float ww = tf[o] + s;
        float p  = pp[o];
        float qq = fmaxf(p, ww);
        float e1 = expf(p  - qq);
        float e2 = expf(ww - qq);
        long idx = (long)b * TDIM * NDIM + o;
        float v  = g_v[idx];
        g_v[idx] = (e1 * aa[o] + e2 * v) / (e1 * bb[o] + e2);
    }
}

// ---- tf32 mma.sync GEMM:  C[M,N] = A[M,K] @ W[N,K]^T
// MODE 0: g_v  = g_xv @ g_wv^T
// MODE 1: g_rv = rna_tf32( sigmoid(g_xr @ g_wr^T) * g_v )
// MODE 2: out  = g_rv @ g_wo^T
template<int MODE>
__global__ void __launch_bounds__(256, 2)
gemm_tf32(float* __restrict__ Cout) {
    const float* __restrict__ A = (MODE == 0) ? g_xv : (MODE == 1) ? g_xr : g_rv;
    const float* __restrict__ W = (MODE == 0) ? g_wv : (MODE == 1) ? g_wr : g_wo;
    float* __restrict__ Cp      = (MODE == 0) ? g_v  : (MODE == 1) ? g_rv : Cout;

    extern __shared__ float sm[];   // [2 stages][A 128x36 | B 128x36]

    const int tid  = threadIdx.x;
    const int lane = tid & 31;
    const int warp = tid >> 5;
    const int wm = warp & 1;          // 2 warps over M (64 rows each)
    const int wn = warp >> 1;         // 4 warps over N (32 cols each)
    const int g  = lane >> 2;
    const int t  = lane & 3;
    const long bm = (long)blockIdx.y * BM;
    const long bn = (long)blockIdx.x * BN;

    float acc[4][4][4];
    #pragma unroll
    for (int i = 0; i < 4; i++)
        #pragma unroll
        for (int j = 0; j < 4; j++)
            #pragma unroll
            for (int k = 0; k < 4; k++) acc[i][j][k] = 0.f;

    const uint32_t sbase = (uint32_t)__cvta_generic_to_shared(sm);

    // cp.async slots: per stage, A = 128 rows x 8 float4 = 1024 slots -> 4/thread
    const int srow = tid >> 3;          // 0..31 (advances by 32 per slot-iter)
    const int scol = (tid & 7) * 4;     // 0,4,...,28 (floats)
    const float* gA = A + (bm + srow) * (long)KDIM + scol;
    const float* gB = W + (bn + srow) * (long)KDIM + scol;
    const uint32_t dOff = (uint32_t)(srow * LSTR + scol) * 4u;

    #define LOAD_STAGE(s, kt) do {                                              \
        uint32_t _a = sbase + (uint32_t)(s) * (STAGE_FLOATS * 4) + dOff;        \
        uint32_t _b = _a + (uint32_t)(MAT_FLOATS * 4);                          \
        int _k = (kt) * BK;                                                     \
        _Pragma("unroll")                                                       \
        for (int _i = 0; _i < 4; _i++) {                                        \
            cp16(_a + (uint32_t)(_i * 32 * LSTR * 4), gA + (long)(_i * 32) * KDIM + _k); \
            cp16(_b + (uint32_t)(_i * 32 * LSTR * 4), gB + (long)(_i * 32) * KDIM + _k); \
        }                                                                        \
        asm volatile("cp.async.commit_group;");                                 \
    } while (0)

    LOAD_STAGE(0, 0);

    for (int kt = 0; kt < NKT; ++kt) {
        asm volatile("cp.async.wait_group 0;" ::: "memory");
        __syncthreads();
        if (kt + 1 < NKT) LOAD_STAGE((kt + 1) & 1, kt + 1);
        const float* As_ = sm + (kt & 1) * STAGE_FLOATS;
        const float* Bs_ = As_ + MAT_FLOATS;
        #pragma unroll
        for (int ks = 0; ks < 4; ks++) {
            float a[4][4], b[4][2];
            #pragma unroll
            for (int im = 0; im < 4; im++) {
                const float* p = As_ + (wm * 64 + im * 16 + g) * LSTR + ks * 8 + t;
                a[im][0] = p[0];
                a[im][1] = p[8 * LSTR];
                a[im][2] = p[4];
                a[im][3] = p[8 * LSTR + 4];
            }
            #pragma unroll
            for (int in = 0; in < 4; in++) {
                const float* p = Bs_ + (wn * 32 + in * 8 + g) * LSTR + ks * 8 + t;
                b[in][0] = p[0];
                b[in][1] = p[4];
            }
            #pragma unroll
            for (int im = 0; im < 4; im++)
                #pragma unroll
                for (int in = 0; in < 4; in++)
                    asm volatile(
                        "mma.sync.aligned.m16n8k8.row.col.f32.tf32.tf32.f32 "
                        "{%0,%1,%2,%3}, {%4,%5,%6,%7}, {%8,%9}, {%0,%1,%2,%3};"
                        : "+f"(acc[im][in][0]), "+f"(acc[im][in][1]),
                          "+f"(acc[im][in][2]), "+f"(acc[im][in][3])
                        : "r"(__float_as_uint(a[im][0])), "r"(__float_as_uint(a[im][1])),
                          "r"(__float_as_uint(a[im][2])), "r"(__float_as_uint(a[im][3])),
                          "r"(__float_as_uint(b[in][0])), "r"(__float_as_uint(b[in][1])));
        }
    }
    #undef LOAD_STAGE

    // Epilogue: c0,c1 contiguous (cols t*2, t*2+1); c2,c3 at row+8.
    #pragma unroll
    for (int im = 0; im < 4; im++) {
        const long m0 = bm + wm * 64 + im * 16 + g;
        #pragma unroll
        for (int in = 0; in < 4; in++) {
            const long n0 = bn + wn * 32 + in * 8 + t * 2;
            const long i0 = m0 * NDIM + n0;
            const long i1 = i0 + 8L * NDIM;
            float c0 = acc[im][in][0], c1 = acc[im][in][1];
            float c2 = acc[im][in][2], c3 = acc[im][in][3];
            if (MODE == 1) {
                float2 v0 = *(const float2*)(g_v + i0);
                float2 v1 = *(const float2*)(g_v + i1);
                float r0 = 1.f / (1.f + __expf(-c0));
                float r1 = 1.f / (1.f + __expf(-c1));
                float r2 = 1.f / (1.f + __expf(-c2));
                float r3 = 1.f / (1.f + __expf(-c3));
                *(float2*)(Cp + i0) = make_float2(rna_tf32(r0 * v0.x), rna_tf32(r1 * v0.y));
                *(float2*)(Cp + i1) = make_float2(rna_tf32(r2 * v1.x), rna_tf32(r3 * v1.y));
            } else {
                *(float2*)(Cp + i0) = make_float2(c0, c1);
                *(float2*)(Cp + i1) = make_float2(c2, c3);
            }
        }
    }
}

extern "C" void kernel_launch(void* const* d_in, const int* in_sizes, int n_in,
                              void* d_out, int out_size) {
    (void)in_sizes; (void)n_in; (void)out_size;
    const float* x   = (const float*)d_in[0];
    const float* tf  = (const float*)d_in[1];
    const float* tmk = (const float*)d_in[2];
    const float* tmv = (const float*)d_in[3];
    const float* tmr = (const float*)d_in[4];
    const float* xxp = (const float*)d_in[5];
    const float* aa  = (const float*)d_in[6];
    const float* bb  = (const float*)d_in[7];
    const float* pp  = (const float*)d_in[8];
    const float* wk  = (const float*)d_in[9];
    const float* wv  = (const float*)d_in[10];
    const float* wr  = (const float*)d_in[11];
    const float* wo  = (const float*)d_in[12];
    float* out = (float*)d_out;

    static bool attr_done = false;
    if (!attr_done) {
        cudaFuncSetAttribute(gemm_tf32<0>, cudaFuncAttributeMaxDynamicSharedMemorySize, DYN_SMEM);
        cudaFuncSetAttribute(gemm_tf32<1>, cudaFuncAttributeMaxDynamicSharedMemorySize, DYN_SMEM);
        cudaFuncSetAttribute(gemm_tf32<2>, cudaFuncAttributeMaxDynamicSharedMemorySize, DYN_SMEM);
        attr_done = true;
    }

    prep_w_kernel<<<(unsigned)(((long)NDIM * KDIM) / 1024), 256>>>(wv, wr, wo);
    prep_x_kernel<<<(unsigned)((MDIM * (long)KDIM) / 1024), 256>>>(x, tmv, tmr, xxp);

    dim3 grid((unsigned)(NDIM / BN), (unsigned)(MDIM / BM));   // (16, 64)
    gemm_tf32<0><<<grid, 256, DYN_SMEM>>>(nullptr);            // g_v = xv @ Wv^T
    t0_fix_kernel<<<dim3(CDIM / 8, BDIM), 256>>>(x, tf, tmk, xxp, aa, bb, pp, wk);
    gemm_tf32<1><<<grid, 256, DYN_SMEM>>>(nullptr);            // g_rv = sig(xr@Wr^T)*g_v
    gemm_tf32<2><<<grid, 256, DYN_SMEM>>>(out);                // out = g_rv @ Wo^T
}